// round 13
// baseline (speedup 1.0000x reference)
#include <cuda_runtime.h>

#define NB 32
#define NS 4096
#define ND 1024
#define NEGV -1e37f

// scratch: logits then softmax weights [B, S]
__device__ float g_logits[NB * NS];

// ---------------------------------------------------------------------------
// Kernel 1: logits[b,s] = q[b] . k[b,s]  (masked rows: skip K read, write NEG)
// 256 threads = 8 warps, each warp one s-row; q[b] staged in shared.
// K loads use __ldcs (evict-first): zero-reuse stream, keeps logits L2-hot.
// Mask is int32 (JAX bool widened): nonzero = valid.
// ---------------------------------------------------------------------------
__global__ __launch_bounds__(256) void qk_kernel(
    const float* __restrict__ keys,
    const float* __restrict__ queries,
    const int* __restrict__ mask)
{
    const int rows_per_block = 8;
    int b  = blockIdx.x / (NS / rows_per_block);
    int s0 = (blockIdx.x % (NS / rows_per_block)) * rows_per_block;

    __shared__ float4 qs[ND / 4];
    qs[threadIdx.x] = ((const float4*)(queries + (size_t)b * ND))[threadIdx.x];
    __syncthreads();

    int warp = threadIdx.x >> 5;
    int lane = threadIdx.x & 31;
    int s = s0 + warp;

    if (mask[b * NS + s] == 0) {
        if (lane == 0) g_logits[b * NS + s] = NEGV;
        return;
    }

    const float4* k4 = (const float4*)(keys + ((size_t)b * NS + s) * ND);
    float acc = 0.f;
#pragma unroll
    for (int i = 0; i < 8; i++) {
        int idx = i * 32 + lane;          // 0..255 float4s
        float4 kv = __ldcs(&k4[idx]);
        float4 qv = qs[idx];
        acc += kv.x * qv.x + kv.y * qv.y + kv.z * qv.z + kv.w * qv.w;
    }
#pragma unroll
    for (int o = 16; o; o >>= 1)
        acc += __shfl_xor_sync(0xFFFFFFFFu, acc, o);

    if (lane == 0) g_logits[b * NS + s] = acc;
}

// ---------------------------------------------------------------------------
// Kernel 2: per-batch softmax over S=4096. One block of 1024 threads per batch.
// Masked logits (-1e37) underflow to exactly 0.0f after exp.
// ---------------------------------------------------------------------------
__global__ __launch_bounds__(1024) void softmax_kernel()
{
    int b = blockIdx.x;
    int t = threadIdx.x;
    float* row = g_logits + b * NS;

    float v0 = row[t];
    float v1 = row[t + 1024];
    float v2 = row[t + 2048];
    float v3 = row[t + 3072];

    __shared__ float red[32];

    // ---- max reduce ----
    float m = fmaxf(fmaxf(v0, v1), fmaxf(v2, v3));
#pragma unroll
    for (int o = 16; o; o >>= 1) m = fmaxf(m, __shfl_xor_sync(0xFFFFFFFFu, m, o));
    if ((t & 31) == 0) red[t >> 5] = m;
    __syncthreads();
    if (t < 32) {
        float x = red[t];
#pragma unroll
        for (int o = 16; o; o >>= 1) x = fmaxf(x, __shfl_xor_sync(0xFFFFFFFFu, x, o));
        red[t] = x;
    }
    __syncthreads();
    m = red[0];
    __syncthreads();

    // ---- exp + sum reduce ----
    float e0 = __expf(v0 - m);
    float e1 = __expf(v1 - m);
    float e2 = __expf(v2 - m);
    float e3 = __expf(v3 - m);
    float s = e0 + e1 + e2 + e3;
#pragma unroll
    for (int o = 16; o; o >>= 1) s += __shfl_xor_sync(0xFFFFFFFFu, s, o);
    if ((t & 31) == 0) red[t >> 5] = s;
    __syncthreads();
    if (t < 32) {
        float x = red[t];
#pragma unroll
        for (int o = 16; o; o >>= 1) x += __shfl_xor_sync(0xFFFFFFFFu, x, o);
        red[t] = x;
    }
    __syncthreads();
    float inv = 1.0f / red[0];

    row[t]        = e0 * inv;
    row[t + 1024] = e1 * inv;
    row[t + 2048] = e2 * inv;
    row[t + 3072] = e3 * inv;
}

// ---------------------------------------------------------------------------
// Kernel 3: PV, D-sliced. Block = (b, 32-float d-slice), 1024 blocks total.
// Stages the batch's 4096 weights in shared (16 KB, L2-hot), then streams its
// 128-byte column slice over all S rows, skipping rows with weight exactly 0.
// Warp layout: 8 threads cover the slice's 8 float4 columns x 4 s-rows ->
// each row segment is one contiguous 128B transaction. Writes out directly
// (fixed-order combine) — no partials, no reduce kernel.
// ---------------------------------------------------------------------------
__global__ __launch_bounds__(256) void pv_kernel(
    const float* __restrict__ values,
    float* __restrict__ out)
{
    int ds = blockIdx.x & 31;          // d-slice index 0..31 (32 floats each)
    int b  = blockIdx.x >> 5;

    __shared__ float  ws[NS];          // 16 KB weights
    __shared__ float4 sp[256];         // combine buffer

    int t = threadIdx.x;
    const float4* wg = (const float4*)(g_logits + b * NS);
#pragma unroll
    for (int i = 0; i < 4; i++)
        ((float4*)ws)[t + 256 * i] = wg[t + 256 * i];
    __syncthreads();

    int d4   = ds * 8 + (t & 7);       // float4 column 0..255
    int srow = t >> 3;                 // 0..31
    const float4* v4 = (const float4*)(values + (size_t)b * NS * ND) + d4;

    float4 acc = make_float4(0.f, 0.f, 0.f, 0.f);
#pragma unroll 4
    for (int i = 0; i < NS / 32; i++) {
        int s = srow + 32 * i;
        float w = ws[s];
        float4 v = make_float4(0.f, 0.f, 0.f, 0.f);
        if (w != 0.f) v = __ldcs(&v4[(size_t)s * (ND / 4)]);
        acc.x += w * v.x; acc.y += w * v.y; acc.z += w * v.z; acc.w += w * v.w;
    }

    sp[t] = acc;
    __syncthreads();

    if (t < 8) {
        float4 r = make_float4(0.f, 0.f, 0.f, 0.f);
#pragma unroll
        for (int k = 0; k < 32; k++) {
            float4 v = sp[t + 8 * k];
            r.x += v.x; r.y += v.y; r.z += v.z; r.w += v.w;
        }
        ((float4*)out)[(size_t)b * (ND / 4) + ds * 8 + t] = r;
    }
}

// ---------------------------------------------------------------------------
extern "C" void kernel_launch(void* const* d_in, const int* in_sizes, int n_in,
                              void* d_out, int out_size)
{
    const float* keys    = (const float*)d_in[0];
    const float* queries = (const float*)d_in[1];
    const float* values  = (const float*)d_in[2];
    const int*   mask    = (const int*)d_in[3];
    float* out = (float*)d_out;

    qk_kernel<<<NB * (NS / 8), 256>>>(keys, queries, mask);
    softmax_kernel<<<NB, 1024>>>();
    pv_kernel<<<NB * 32, 256>>>(values, out);
}

// round 14
// speedup vs baseline: 1.2837x; 1.2837x over previous
#include <cuda_runtime.h>

#define NB 32
#define NS 4096
#define ND 1024
#define NEGV -1e37f

#define SCHUNK 128
#define NCH (NS / SCHUNK)   // 32
#define NBH (NB / 2)        // 16 batches per stream-group

// scratch: logits then softmax weights [B, S]
__device__ float g_logits[NB * NS];
// partial PV sums [B, NCH, D]
__device__ float g_part[NB * NCH * ND];

// ---------------------------------------------------------------------------
// Kernel 1: logits[b,s] = q[b] . k[b,s]  (masked rows: skip K read, write NEG)
// 256 threads = 8 warps, each warp one s-row; q[b] staged in shared.
// K loads use __ldcs (evict-first). Mask is int32: nonzero = valid.
// ---------------------------------------------------------------------------
__global__ __launch_bounds__(256) void qk_kernel(
    const float* __restrict__ keys,
    const float* __restrict__ queries,
    const int* __restrict__ mask,
    int b0)
{
    const int rows_per_block = 8;
    int b  = b0 + blockIdx.x / (NS / rows_per_block);
    int s0 = (blockIdx.x % (NS / rows_per_block)) * rows_per_block;

    __shared__ float4 qs[ND / 4];
    qs[threadIdx.x] = ((const float4*)(queries + (size_t)b * ND))[threadIdx.x];
    __syncthreads();

    int warp = threadIdx.x >> 5;
    int lane = threadIdx.x & 31;
    int s = s0 + warp;

    if (mask[b * NS + s] == 0) {
        if (lane == 0) g_logits[b * NS + s] = NEGV;
        return;
    }

    const float4* k4 = (const float4*)(keys + ((size_t)b * NS + s) * ND);
    float acc = 0.f;
#pragma unroll
    for (int i = 0; i < 8; i++) {
        int idx = i * 32 + lane;          // 0..255 float4s
        float4 kv = __ldcs(&k4[idx]);
        float4 qv = qs[idx];
        acc += kv.x * qv.x + kv.y * qv.y + kv.z * qv.z + kv.w * qv.w;
    }
#pragma unroll
    for (int o = 16; o; o >>= 1)
        acc += __shfl_xor_sync(0xFFFFFFFFu, acc, o);

    if (lane == 0) g_logits[b * NS + s] = acc;
}

// ---------------------------------------------------------------------------
// Kernel 2: per-batch softmax over S=4096. One block of 1024 threads per batch.
// Masked logits (-1e37) underflow to exactly 0.0f after exp.
// ---------------------------------------------------------------------------
__global__ __launch_bounds__(1024) void softmax_kernel(int b0)
{
    int b = b0 + blockIdx.x;
    int t = threadIdx.x;
    float* row = g_logits + b * NS;

    float v0 = row[t];
    float v1 = row[t + 1024];
    float v2 = row[t + 2048];
    float v3 = row[t + 3072];

    __shared__ float red[32];

    // ---- max reduce ----
    float m = fmaxf(fmaxf(v0, v1), fmaxf(v2, v3));
#pragma unroll
    for (int o = 16; o; o >>= 1) m = fmaxf(m, __shfl_xor_sync(0xFFFFFFFFu, m, o));
    if ((t & 31) == 0) red[t >> 5] = m;
    __syncthreads();
    if (t < 32) {
        float x = red[t];
#pragma unroll
        for (int o = 16; o; o >>= 1) x = fmaxf(x, __shfl_xor_sync(0xFFFFFFFFu, x, o));
        red[t] = x;
    }
    __syncthreads();
    m = red[0];
    __syncthreads();

    // ---- exp + sum reduce ----
    float e0 = __expf(v0 - m);
    float e1 = __expf(v1 - m);
    float e2 = __expf(v2 - m);
    float e3 = __expf(v3 - m);
    float s = e0 + e1 + e2 + e3;
#pragma unroll
    for (int o = 16; o; o >>= 1) s += __shfl_xor_sync(0xFFFFFFFFu, s, o);
    if ((t & 31) == 0) red[t >> 5] = s;
    __syncthreads();
    if (t < 32) {
        float x = red[t];
#pragma unroll
        for (int o = 16; o; o >>= 1) x += __shfl_xor_sync(0xFFFFFFFFu, x, o);
        red[t] = x;
    }
    __syncthreads();
    float inv = 1.0f / red[0];

    row[t]        = e0 * inv;
    row[t + 1024] = e1 * inv;
    row[t + 2048] = e2 * inv;
    row[t + 3072] = e3 * inv;
}

// ---------------------------------------------------------------------------
// Kernel 3: partial PV. Block = (b, 128-row s-chunk). 256 threads, each owns a
// float4 of D. Skips V rows whose weight is exactly 0. V loads __ldcs.
// ---------------------------------------------------------------------------
__global__ __launch_bounds__(256) void pv_kernel(
    const float* __restrict__ values, int b0)
{
    int chunk = blockIdx.x & (NCH - 1);
    int b     = b0 + blockIdx.x / NCH;
    int s0    = chunk * SCHUNK;

    __shared__ float ws[SCHUNK];
    int t = threadIdx.x;
    if (t < SCHUNK) ws[t] = g_logits[b * NS + s0 + t];
    __syncthreads();

    const float4* v4 = (const float4*)(values + ((size_t)b * NS + s0) * ND);
    float4 acc = make_float4(0.f, 0.f, 0.f, 0.f);

#pragma unroll 4
    for (int i = 0; i < SCHUNK; i += 4) {
        float w0 = ws[i], w1 = ws[i + 1], w2 = ws[i + 2], w3 = ws[i + 3];
        float4 a = make_float4(0.f, 0.f, 0.f, 0.f);
        float4 c = make_float4(0.f, 0.f, 0.f, 0.f);
        float4 d = make_float4(0.f, 0.f, 0.f, 0.f);
        float4 e = make_float4(0.f, 0.f, 0.f, 0.f);
        if (w0 != 0.f) a = __ldcs(&v4[(size_t)(i + 0) * (ND / 4) + t]);
        if (w1 != 0.f) c = __ldcs(&v4[(size_t)(i + 1) * (ND / 4) + t]);
        if (w2 != 0.f) d = __ldcs(&v4[(size_t)(i + 2) * (ND / 4) + t]);
        if (w3 != 0.f) e = __ldcs(&v4[(size_t)(i + 3) * (ND / 4) + t]);
        acc.x += w0 * a.x; acc.y += w0 * a.y; acc.z += w0 * a.z; acc.w += w0 * a.w;
        acc.x += w1 * c.x; acc.y += w1 * c.y; acc.z += w1 * c.z; acc.w += w1 * c.w;
        acc.x += w2 * d.x; acc.y += w2 * d.y; acc.z += w2 * d.z; acc.w += w2 * d.w;
        acc.x += w3 * e.x; acc.y += w3 * e.y; acc.z += w3 * e.z; acc.w += w3 * e.w;
    }

    ((float4*)g_part)[(size_t)(b * NCH + chunk) * (ND / 4) + t] = acc;
}

// ---------------------------------------------------------------------------
// Kernel 4: out[b,:] = sum over 32 chunks of g_part[b,c,:].
// 128 blocks per group x 256 threads; 8 threads cooperate per float4 output.
// ---------------------------------------------------------------------------
__global__ __launch_bounds__(256) void reduce_kernel(float* __restrict__ out, int b0)
{
    int t    = threadIdx.x;
    int oct  = t >> 5;                 // 0..7 chunk-octant
    int slot = t & 31;                 // 0..31 output slot within block
    int o  = b0 * (ND / 4) + blockIdx.x * 32 + slot;   // global float4 index
    int b  = o >> 8;                   // ND/4 = 256 float4 per batch
    int d4 = o & 255;

    const float4* p4 = (const float4*)g_part + ((size_t)b * NCH) * (ND / 4) + d4;

    float4 acc = make_float4(0.f, 0.f, 0.f, 0.f);
#pragma unroll
    for (int c = 0; c < 4; c++) {
        float4 v = p4[(size_t)(oct * 4 + c) * (ND / 4)];
        acc.x += v.x; acc.y += v.y; acc.z += v.z; acc.w += v.w;
    }

    __shared__ float4 sp[7 * 32];      // octants 1..7
    if (oct > 0) sp[(oct - 1) * 32 + slot] = acc;
    __syncthreads();

    if (oct == 0) {
#pragma unroll
        for (int i = 0; i < 7; i++) {
            float4 v = sp[i * 32 + slot];
            acc.x += v.x; acc.y += v.y; acc.z += v.z; acc.w += v.w;
        }
        ((float4*)out)[o] = acc;
    }
}

// ---------------------------------------------------------------------------
// Two-stream fork-join: group 0 (batches 0-15) on s1, group 1 (16-31) on s2.
// Streams/events created lazily once (no device memory involved). The fork
// from and join back to the harness's capture stream use the documented
// event-based capture pattern.
// ---------------------------------------------------------------------------
extern "C" void kernel_launch(void* const* d_in, const int* in_sizes, int n_in,
                              void* d_out, int out_size)
{
    const float* keys    = (const float*)d_in[0];
    const float* queries = (const float*)d_in[1];
    const float* values  = (const float*)d_in[2];
    const int*   mask    = (const int*)d_in[3];
    float* out = (float*)d_out;

    static cudaStream_t s1 = nullptr, s2 = nullptr;
    static cudaEvent_t  e0 = nullptr, e1 = nullptr, e2 = nullptr;
    if (s1 == nullptr) {
        cudaStreamCreateWithFlags(&s1, cudaStreamNonBlocking);
        cudaStreamCreateWithFlags(&s2, cudaStreamNonBlocking);
        cudaEventCreateWithFlags(&e0, cudaEventDisableTiming);
        cudaEventCreateWithFlags(&e1, cudaEventDisableTiming);
        cudaEventCreateWithFlags(&e2, cudaEventDisableTiming);
    }

    // fork
    cudaEventRecord(e0, 0);
    cudaStreamWaitEvent(s1, e0, 0);
    cudaStreamWaitEvent(s2, e0, 0);

    // group 0 on s1
    qk_kernel<<<NBH * (NS / 8), 256, 0, s1>>>(keys, queries, mask, 0);
    softmax_kernel<<<NBH, 1024, 0, s1>>>(0);
    pv_kernel<<<NBH * NCH, 256, 0, s1>>>(values, 0);
    reduce_kernel<<<NBH * (ND / 4) / 32, 256, 0, s1>>>(out, 0);

    // group 1 on s2
    qk_kernel<<<NBH * (NS / 8), 256, 0, s2>>>(keys, queries, mask, NBH);
    softmax_kernel<<<NBH, 1024, 0, s2>>>(NBH);
    pv_kernel<<<NBH * NCH, 256, 0, s2>>>(values, NBH);
    reduce_kernel<<<NBH * (ND / 4) / 32, 256, 0, s2>>>(out, NBH);

    // join
    cudaEventRecord(e1, s1);
    cudaEventRecord(e2, s2);
    cudaStreamWaitEvent(0, e1, 0);
    cudaStreamWaitEvent(0, e2, 0);
}